// round 3
// baseline (speedup 1.0000x reference)
#include <cuda_runtime.h>
#include <cuda_bf16.h>
#include <cstddef>

// ---------------------------------------------------------------------------
// LuongAttnDecoderMogLSTM  (B=128, H=1024, S=512, V=32000, MOG=5)
// fp32 baseline: feature-major [K][B] intermediates, split-K GEMMs,
// fused online-softmax attention (single pass over encoder_outputs).
// ---------------------------------------------------------------------------

#define Bq   128
#define Hq   1024
#define Sq   512
#define Vq   32000

static __device__ float g_xT [Hq*Bq];
static __device__ float g_hT [Hq*Bq];
static __device__ float g_cT [Hq*Bq];
static __device__ float g_rnnT[Hq*Bq];
static __device__ float g_ctxT[Hq*Bq];
static __device__ float g_ccT [Hq*Bq];
static __device__ float g_gates[4*Hq*Bq];
static __device__ float g_part [4*4096*Bq];      // split-K partials (8 MB)
static __device__ float g_logits[(size_t)Bq*Vq]; // 16 MB

__device__ __forceinline__ float sigf(float x) { return 1.f / (1.f + expf(-x)); }

// ----------------------------- transpose ----------------------------------
// src [R][C] -> dst [C][R]; grid (C/32, R/32), block (32,8)
__global__ void transpose_kernel(const float* __restrict__ src,
                                 float* __restrict__ dst, int R, int C)
{
    __shared__ float t[32][33];
    int c0 = blockIdx.x * 32, r0 = blockIdx.y * 32;
    #pragma unroll
    for (int i = threadIdx.y; i < 32; i += 8)
        t[i][threadIdx.x] = src[(size_t)(r0 + i) * C + c0 + threadIdx.x];
    __syncthreads();
    #pragma unroll
    for (int i = threadIdx.y; i < 32; i += 8)
        dst[(size_t)(c0 + i) * R + r0 + threadIdx.x] = t[threadIdx.x][i];
}

// ----------------------------- embedding ----------------------------------
// xT[h][b] = emb[step[b]][h]
__global__ void embed_kernel(const int* __restrict__ step,
                             const float* __restrict__ emb,
                             float* __restrict__ xT)
{
    int idx = blockIdx.x * blockDim.x + threadIdx.x;   // h*128 + b
    if (idx >= Hq * Bq) return;
    int h = idx >> 7, b = idx & 127;
    xT[idx] = emb[(size_t)step[b] * Hq + h];
}

// ----------------------------- GEMM ---------------------------------------
// C[n][b] (partials) or Cfinal[b][n] (+bias) = sum_k At[k][b] * W[n][wcol0+k]
// At: [K][128]. W row-major with leading dim ldw.
// grid: (N/64, KS).  block 256 threads: tx=tid&15 (8 b's), ty=tid>>4 (4 n's).
#define KC 16
__global__ void __launch_bounds__(256)
gemm_kernel(const float* __restrict__ At, const float* __restrict__ W,
            int ldw, int wcol0,
            float* __restrict__ Cp, int slice0, int K,
            const float* __restrict__ bias_f, float* __restrict__ Cfinal)
{
    __shared__ float As[KC][128];
    __shared__ float Ws[KC][68];

    int n0  = blockIdx.x * 64;
    int N   = gridDim.x * 64;
    int KS  = gridDim.y;
    int klen = K / KS;
    int kbeg = blockIdx.y * klen;

    int tid = threadIdx.x;
    int tx = tid & 15;   // b-group: b = tx*8 .. tx*8+7
    int ty = tid >> 4;   // n-group: n = n0 + ty*4 .. +3

    float acc[8][4];
    #pragma unroll
    for (int i = 0; i < 8; i++)
        #pragma unroll
        for (int j = 0; j < 4; j++) acc[i][j] = 0.f;

    for (int kc = kbeg; kc < kbeg + klen; kc += KC) {
        // A tile: 16x128 floats, 2 float4 per thread, coalesced, conflict-free
        #pragma unroll
        for (int i = 0; i < 2; i++) {
            int f  = tid + 256 * i;           // float4 index 0..511
            int kk = f >> 5;
            int b4 = (f & 31) << 2;
            *(float4*)&As[kk][b4] = *(const float4*)&At[(size_t)(kc + kk) * 128 + b4];
        }
        // W tile: 64 n x 16 k, transposed into Ws[k][n]
        {
            int n  = tid >> 2;
            int kk = (tid & 3) << 2;
            float4 w4 = *(const float4*)&W[(size_t)(n0 + n) * ldw + wcol0 + kc + kk];
            Ws[kk + 0][n] = w4.x; Ws[kk + 1][n] = w4.y;
            Ws[kk + 2][n] = w4.z; Ws[kk + 3][n] = w4.w;
        }
        __syncthreads();
        #pragma unroll
        for (int k = 0; k < KC; k++) {
            float a[8], w[4];
            *(float4*)&a[0] = *(float4*)&As[k][tx * 8];
            *(float4*)&a[4] = *(float4*)&As[k][tx * 8 + 4];
            *(float4*)&w[0] = *(float4*)&Ws[k][ty * 4];
            #pragma unroll
            for (int j = 0; j < 4; j++)
                #pragma unroll
                for (int i = 0; i < 8; i++) acc[i][j] += a[i] * w[j];
        }
        __syncthreads();
    }

    if (Cfinal) {                 // final row-major write with bias
        #pragma unroll
        for (int i = 0; i < 8; i++) {
            int b = tx * 8 + i;
            int n = n0 + ty * 4;
            float4 v = make_float4(acc[i][0] + bias_f[n + 0],
                                   acc[i][1] + bias_f[n + 1],
                                   acc[i][2] + bias_f[n + 2],
                                   acc[i][3] + bias_f[n + 3]);
            *(float4*)&Cfinal[(size_t)b * N + n] = v;
        }
    } else {                      // partial write [slice][n][b]
        float* out = Cp + (size_t)(slice0 + blockIdx.y) * N * 128;
        #pragma unroll
        for (int j = 0; j < 4; j++) {
            int n = n0 + ty * 4 + j;
            #pragma unroll
            for (int i = 0; i < 8; i += 4) {
                float4 v = make_float4(acc[i][j], acc[i+1][j], acc[i+2][j], acc[i+3][j]);
                *(float4*)&out[(size_t)n * 128 + tx * 8 + i] = v;
            }
        }
    }
}

// ------------------------ split-K reduce + epilogue ------------------------
// EPI: 0 = bias(+bias2) plain, 1 = mogrifier (out *= 2*sigmoid(v+bias)), 2 = tanh
template<int EPI>
__global__ void epi_kernel(const float* __restrict__ Cp, int nsl, int N,
                           const float* __restrict__ bias,
                           const float* __restrict__ bias2,
                           float* __restrict__ out)
{
    int idx = blockIdx.x * blockDim.x + threadIdx.x;    // n*128 + b
    if (idx >= N * 128) return;
    int n = idx >> 7;
    float v = 0.f;
    for (int s = 0; s < nsl; s++) v += Cp[(size_t)s * N * 128 + idx];
    if (bias)  v += bias[n];
    if (bias2) v += bias2[n];
    if (EPI == 0)      out[idx]  = v;
    else if (EPI == 1) out[idx] *= 2.f * sigf(v);
    else               out[idx]  = tanhf(v);
}

// --------------------------- LSTM pointwise --------------------------------
// gates [4H][B], order i,f,g,o. layer2: c_prev = 0 (skip f term).
__global__ void lstm_pointwise(const float* __restrict__ gates,
                               const float* __restrict__ cT,
                               float* __restrict__ hT, int layer2)
{
    int idx = blockIdx.x * blockDim.x + threadIdx.x;
    if (idx >= Hq * Bq) return;
    float ig = gates[idx];
    float fg = gates[Hq * Bq + idx];
    float gg = gates[2 * Hq * Bq + idx];
    float og = gates[3 * Hq * Bq + idx];
    float c  = layer2 ? sigf(ig) * tanhf(gg)
                      : sigf(fg) * cT[idx] + sigf(ig) * tanhf(gg);
    hT[idx] = sigf(og) * tanhf(c);
}

// -------------------- layer-2 mogrifier (exact, bias-only) -----------------
// With h2=0: h stays 0 through all 5 steps; x *= 2s(b0)*2s(b2)*2s(b4).
__global__ void mog2_scale(const float* __restrict__ hT,
                           const float* __restrict__ mog2_b,
                           float* __restrict__ xT)
{
    int idx = blockIdx.x * blockDim.x + threadIdx.x;
    if (idx >= Hq * Bq) return;
    int j = idx >> 7;
    float f = 8.f * sigf(mog2_b[j]) * sigf(mog2_b[2 * Hq + j]) * sigf(mog2_b[4 * Hq + j]);
    xT[idx] = hT[idx] * f;
}

// --------------------- fused attention (online softmax) --------------------
// One block per b. 8 warps; warp w handles s = w, w+8, ... (64 rows each).
// Single pass over encoder_outputs (268 MB), flash-style accumulator merge.
__global__ void __launch_bounds__(256)
attention_kernel(const float* __restrict__ rnnT,   // [H][B]
                 const float* __restrict__ enc,    // [S][B][H]
                 float* __restrict__ ctxT)         // [H][B]
{
    int b    = blockIdx.x;
    int tid  = threadIdx.x;
    int w    = tid >> 5;
    int lane = tid & 31;

    float q[32];
    #pragma unroll
    for (int i = 0; i < 32; i++) q[i] = rnnT[(size_t)(i * 32 + lane) * Bq + b];

    float m = -1e30f, l = 0.f, acc[32];
    #pragma unroll
    for (int i = 0; i < 32; i++) acc[i] = 0.f;

    for (int s = w; s < Sq; s += 8) {
        const float* e = enc + ((size_t)s * Bq + b) * Hq;
        float ev[32], dot = 0.f;
        #pragma unroll
        for (int i = 0; i < 32; i++) { ev[i] = e[i * 32 + lane]; dot += q[i] * ev[i]; }
        #pragma unroll
        for (int o = 16; o > 0; o >>= 1) dot += __shfl_xor_sync(0xffffffffu, dot, o);
        float mn   = fmaxf(m, dot);
        float corr = expf(m - mn);
        float p    = expf(dot - mn);
        l = l * corr + p;
        #pragma unroll
        for (int i = 0; i < 32; i++) acc[i] = acc[i] * corr + p * ev[i];
        m = mn;
    }

    __shared__ float sm[8], sl[8];
    __shared__ float sacc[8][Hq];
    #pragma unroll
    for (int i = 0; i < 32; i++) sacc[w][i * 32 + lane] = acc[i];
    if (lane == 0) { sm[w] = m; sl[w] = l; }
    __syncthreads();

    float M = -1e30f;
    #pragma unroll
    for (int ww = 0; ww < 8; ww++) M = fmaxf(M, sm[ww]);
    float wexp[8], L = 0.f;
    #pragma unroll
    for (int ww = 0; ww < 8; ww++) { wexp[ww] = expf(sm[ww] - M); L += sl[ww] * wexp[ww]; }
    float invL = 1.f / L;

    for (int h = tid; h < Hq; h += 256) {
        float v = 0.f;
        #pragma unroll
        for (int ww = 0; ww < 8; ww++) v += sacc[ww][h] * wexp[ww];
        ctxT[(size_t)h * Bq + b] = v * invL;
    }
}

// ------------------------------ row softmax --------------------------------
__global__ void softmax_kernel(const float* __restrict__ logits,
                               float* __restrict__ out)
{
    int b = blockIdx.x, tid = threadIdx.x;
    const float* row = logits + (size_t)b * Vq;
    __shared__ float red[256];

    float mx = -1e30f;
    for (int v = tid; v < Vq; v += 256) mx = fmaxf(mx, row[v]);
    red[tid] = mx; __syncthreads();
    for (int st = 128; st > 0; st >>= 1) {
        if (tid < st) red[tid] = fmaxf(red[tid], red[tid + st]);
        __syncthreads();
    }
    mx = red[0]; __syncthreads();

    float sum = 0.f;
    for (int v = tid; v < Vq; v += 256) sum += expf(row[v] - mx);
    red[tid] = sum; __syncthreads();
    for (int st = 128; st > 0; st >>= 1) {
        if (tid < st) red[tid] += red[tid + st];
        __syncthreads();
    }
    float inv = 1.f / red[0];

    float* o = out + (size_t)b * Vq;
    for (int v = tid; v < Vq; v += 256) o[v] = expf(row[v] - mx) * inv;
}

// ------------------------------- launch ------------------------------------
extern "C" void kernel_launch(void* const* d_in, const int* in_sizes, int n_in,
                              void* d_out, int out_size)
{
    const int*   step  = (const int*)  d_in[0];
    const float* enc   = (const float*)d_in[1];
    const float* h1    = (const float*)d_in[2];
    const float* c1    = (const float*)d_in[3];
    const float* emb   = (const float*)d_in[4];
    const float* mog1W = (const float*)d_in[5];
    const float* mog1b = (const float*)d_in[6];
    const float* Wih1  = (const float*)d_in[7];
    const float* Whh1  = (const float*)d_in[8];
    const float* bih1  = (const float*)d_in[9];
    const float* bhh1  = (const float*)d_in[10];
    const float* mog2b = (const float*)d_in[12];
    const float* Wih2  = (const float*)d_in[13];
    const float* bih2  = (const float*)d_in[15];
    const float* bhh2  = (const float*)d_in[16];
    const float* fcW   = (const float*)d_in[17];
    const float* fcb   = (const float*)d_in[18];
    const float* ccW   = (const float*)d_in[19];
    const float* ccb   = (const float*)d_in[20];
    const float* outW  = (const float*)d_in[21];
    const float* outb  = (const float*)d_in[22];
    float* out = (float*)d_out;

    float *xT, *hT, *cT, *rnnT, *ctxT, *ccT, *gates, *part, *logits;
    cudaGetSymbolAddress((void**)&xT,    g_xT);
    cudaGetSymbolAddress((void**)&hT,    g_hT);
    cudaGetSymbolAddress((void**)&cT,    g_cT);
    cudaGetSymbolAddress((void**)&rnnT,  g_rnnT);
    cudaGetSymbolAddress((void**)&ctxT,  g_ctxT);
    cudaGetSymbolAddress((void**)&ccT,   g_ccT);
    cudaGetSymbolAddress((void**)&gates, g_gates);
    cudaGetSymbolAddress((void**)&part,  g_part);
    cudaGetSymbolAddress((void**)&logits,g_logits);

    dim3 tb(32, 8);
    // state -> feature-major scratch copies
    transpose_kernel<<<dim3(Hq/32, Bq/32), tb>>>(h1, hT, Bq, Hq);
    transpose_kernel<<<dim3(Hq/32, Bq/32), tb>>>(c1, cT, Bq, Hq);
    embed_kernel<<<(Hq*Bq)/256, 256>>>(step, emb, xT);

    // layer-1 mogrifier: i even -> g(hT) scales xT; i odd -> g(xT) scales hT
    for (int i = 0; i < 5; i++) {
        const float* src = (i % 2 == 0) ? hT : xT;
        float*       tgt = (i % 2 == 0) ? xT : hT;
        gemm_kernel<<<dim3(16, 8), 256>>>(src, mog1W + (size_t)i*Hq*Hq, Hq, 0,
                                          part, 0, Hq, nullptr, nullptr);
        epi_kernel<1><<<(Hq*Bq)/256, 256>>>(part, 8, Hq, mog1b + i*Hq, nullptr, tgt);
    }

    // layer-1 LSTM gates: x@Wih^T + h@Whh^T + bih + bhh
    gemm_kernel<<<dim3(64, 2), 256>>>(xT, Wih1, Hq, 0, part, 0, Hq, nullptr, nullptr);
    gemm_kernel<<<dim3(64, 2), 256>>>(hT, Whh1, Hq, 0, part, 2, Hq, nullptr, nullptr);
    epi_kernel<0><<<(4*Hq*Bq)/256, 256>>>(part, 4, 4*Hq, bih1, bhh1, gates);
    lstm_pointwise<<<(Hq*Bq)/256, 256>>>(gates, cT, hT, 0);   // hT := h1n

    // layer-2: mogrifier collapses to bias-only scaling (h2=0 exactly)
    mog2_scale<<<(Hq*Bq)/256, 256>>>(hT, mog2b, xT);
    gemm_kernel<<<dim3(64, 2), 256>>>(xT, Wih2, Hq, 0, part, 0, Hq, nullptr, nullptr);
    epi_kernel<0><<<(4*Hq*Bq)/256, 256>>>(part, 2, 4*Hq, bih2, bhh2, gates);
    lstm_pointwise<<<(Hq*Bq)/256, 256>>>(gates, nullptr, hT, 1);  // hT := h2n

    // fc
    gemm_kernel<<<dim3(16, 8), 256>>>(hT, fcW, Hq, 0, part, 0, Hq, nullptr, nullptr);
    epi_kernel<0><<<(Hq*Bq)/256, 256>>>(part, 8, Hq, fcb, nullptr, rnnT);

    // fused Luong attention (single pass over enc)
    attention_kernel<<<Bq, 256>>>(rnnT, enc, ctxT);

    // concat: [rnn_out, context] @ concat_W^T -> tanh
    gemm_kernel<<<dim3(16, 4), 256>>>(rnnT, ccW, 2*Hq, 0,  part, 0, Hq, nullptr, nullptr);
    gemm_kernel<<<dim3(16, 4), 256>>>(ctxT, ccW, 2*Hq, Hq, part, 4, Hq, nullptr, nullptr);
    epi_kernel<2><<<(Hq*Bq)/256, 256>>>(part, 8, Hq, ccb, nullptr, ccT);

    // output projection (direct row-major write with bias) + softmax
    gemm_kernel<<<dim3(Vq/64, 1), 256>>>(ccT, outW, Hq, 0, nullptr, 0, Hq, outb, logits);
    softmax_kernel<<<Bq, 256>>>(logits, out);

    // hidden = h2n, row-major [B][H] appended after the softmax output
    if (out_size >= Bq*Vq + Bq*Hq)
        transpose_kernel<<<dim3(Bq/32, Hq/32), tb>>>(hT, out + (size_t)Bq*Vq, Hq, Bq);
}

// round 9
// speedup vs baseline: 2.0282x; 2.0282x over previous
#include <cuda_runtime.h>
#include <cuda_bf16.h>
#include <cstdint>
#include <cstddef>

// ---------------------------------------------------------------------------
// LuongAttnDecoderMogLSTM  (B=128, H=1024, S=512, V=32000, MOG=5)
// Round 5: all GEMMs on mma.sync bf16 HMMA (bf16x3 hi/lo split, fp32 accum in
// registers). Row-major [B][K] activations. Fused flash attention.
// ---------------------------------------------------------------------------

#define Bq 128
#define Hq 1024
#define Sq 512
#define Vq 32000

static __device__ float g_x   [Bq*Hq];
static __device__ float g_h   [Bq*Hq];
static __device__ float g_rnn [Bq*Hq];
static __device__ float g_ctx [Bq*Hq];
static __device__ float g_cc  [Bq*Hq];
static __device__ float g_gates[Bq*4*Hq];
static __device__ float g_part[8*4096*Bq];        // split-K partials (16.8 MB)
static __device__ float g_logits[(size_t)Bq*Vq];  // 16 MB

__device__ __forceinline__ float sigf(float x) { return 1.f / (1.f + expf(-x)); }

__device__ __forceinline__ uint32_t smem_u32(const void* p) {
    uint32_t a;
    asm("{ .reg .u64 t; cvta.to.shared.u64 t, %1; cvt.u32.u64 %0, t; }"
        : "=r"(a) : "l"(p));
    return a;
}

__device__ __forceinline__ uint32_t lds32(uint32_t a) {
    uint32_t v;
    asm volatile("ld.shared.b32 %0, [%1];" : "=r"(v) : "r"(a));
    return v;
}

#define STS128(addr, a, b, c, d) \
    asm volatile("st.shared.v4.b32 [%0], {%1, %2, %3, %4};" \
                 :: "r"(addr), "r"(a), "r"(b), "r"(c), "r"(d) : "memory")

// fp32 -> bf16 hi/lo split (round-to-nearest-even)
__device__ __forceinline__ void split_bf(float f, uint32_t& hb, uint32_t& lb) {
    uint32_t u  = __float_as_uint(f);
    uint32_t hr = (u + 0x7FFFu + ((u >> 16) & 1u)) & 0xFFFF0000u;
    float    lf = f - __uint_as_float(hr);
    uint32_t ul = __float_as_uint(lf);
    uint32_t lr = (ul + 0x7FFFu + ((ul >> 16) & 1u)) & 0xFFFF0000u;
    hb = hr >> 16;  lb = lr >> 16;
}

// Convert 32 fp32 (row r, cols cg..cg+31 of a 128x64 tile) from registers,
// store SW128-swizzled bf16 pairs into hi and lo smem tiles (16 KB each).
__device__ __forceinline__ void cvt_sts8(const float4* f, uint32_t dhi,
                                         uint32_t dlo, int r, int cg)
{
    #pragma unroll
    for (int g = 0; g < 4; g++) {
        float4 f0 = f[2 * g], f1 = f[2 * g + 1];
        uint32_t h[8], l[8];
        split_bf(f0.x, h[0], l[0]); split_bf(f0.y, h[1], l[1]);
        split_bf(f0.z, h[2], l[2]); split_bf(f0.w, h[3], l[3]);
        split_bf(f1.x, h[4], l[4]); split_bf(f1.y, h[5], l[5]);
        split_bf(f1.z, h[6], l[6]); split_bf(f1.w, h[7], l[7]);
        uint32_t p0 = h[0] | (h[1] << 16), p1 = h[2] | (h[3] << 16);
        uint32_t p2 = h[4] | (h[5] << 16), p3 = h[6] | (h[7] << 16);
        uint32_t q0 = l[0] | (l[1] << 16), q1 = l[2] | (l[3] << 16);
        uint32_t q2 = l[4] | (l[5] << 16), q3 = l[6] | (l[7] << 16);
        uint32_t byte = (uint32_t)r * 128u + (uint32_t)(cg + g * 8) * 2u;
        uint32_t sw = byte ^ ((byte >> 3) & 0x70u);
        STS128(dhi + sw, p0, p1, p2, p3);
        STS128(dlo + sw, q0, q1, q2, q3);
    }
}

// Address of a 4-byte fragment word in a SW128 128x64-bf16 tile.
__device__ __forceinline__ uint32_t fragaddr(uint32_t base, int row, int bo) {
    int unit = bo >> 4;
    return base + (uint32_t)row * 128u
                + (uint32_t)(((unit ^ (row & 7)) << 4) | (bo & 15));
}

#define MMA_BF16(d, a, b0_, b1_) \
    asm volatile("mma.sync.aligned.m16n8k16.row.col.f32.bf16.bf16.f32 " \
        "{%0,%1,%2,%3}, {%4,%5,%6,%7}, {%8,%9}, {%0,%1,%2,%3};" \
        : "+f"((d)[0]), "+f"((d)[1]), "+f"((d)[2]), "+f"((d)[3]) \
        : "r"((a)[0]), "r"((a)[1]), "r"((a)[2]), "r"((a)[3]), \
          "r"(b0_), "r"(b1_))

// ============================ mma_gemm =====================================
// C[b][n] = sum_k A[b][k] * W[n][wcol0+k]   (M=128, n-tile=128, k-chunk=64)
// bf16x3: hi*hi + lo*hi + hi*lo, fp32 register accumulators.
// grid (N/128, KS); klen = K/KS (multiple of 64).
// Cfinal!=0: row-major [b][Nf] with bias. else: partials [slice0+by][b][Np].
// smem buffer: Ah@0, Al@16K, Wh@32K, Wl@48K; double buffered (128 KB).

#define GBUF 65536u
#define SMEM_BYTES (2 * 65536)

__global__ void __launch_bounds__(256, 1)
mma_gemm(const float* __restrict__ A, int lda,
         const float* __restrict__ W, int ldw, int wcol0, int klen,
         float* __restrict__ Cp, int slice0, int Np,
         const float* __restrict__ bias, float* __restrict__ Cfinal, int Nf)
{
    extern __shared__ char smem[];
    const uint32_t sb = smem_u32(smem);
    const int tid  = threadIdx.x;
    const int lane = tid & 31;
    const int wid  = tid >> 5;
    const int n0   = blockIdx.x * 128;
    const int kbeg = blockIdx.y * klen;
    const int T    = klen >> 6;

    const int r  = tid >> 1;
    const int cg = (tid & 1) * 32;
    const float* Agp = A + (size_t)r * lda + kbeg + cg;
    const float* Wgp = W + (size_t)(n0 + r) * ldw + wcol0 + kbeg + cg;

    float4 fa[8], fw[8];
    #pragma unroll
    for (int i = 0; i < 8; i++) {
        fa[i] = *(const float4*)(Agp + i * 4);
        fw[i] = *(const float4*)(Wgp + i * 4);
    }

    const int wm = (wid & 3) * 32;      // warp m-tile origin (rows)
    const int wn = (wid >> 2) * 64;     // warp n-tile origin (cols)

    float acc[2][8][4];
    #pragma unroll
    for (int mf = 0; mf < 2; mf++)
        #pragma unroll
        for (int nf = 0; nf < 8; nf++)
            #pragma unroll
            for (int j = 0; j < 4; j++) acc[mf][nf][j] = 0.f;

    for (int t = 0; t < T; t++) {
        uint32_t base = sb + (uint32_t)(t & 1) * GBUF;
        cvt_sts8(fa, base,           base + 16384u, r, cg);
        cvt_sts8(fw, base + 32768u,  base + 49152u, r, cg);
        __syncthreads();

        if (t + 1 < T) {   // prefetch next chunk into registers
            #pragma unroll
            for (int i = 0; i < 8; i++) {
                fa[i] = *(const float4*)(Agp + (t + 1) * 64 + i * 4);
                fw[i] = *(const float4*)(Wgp + (t + 1) * 64 + i * 4);
            }
        }

        #pragma unroll
        for (int kf = 0; kf < 4; kf++) {
            const int bo = kf * 32 + (lane & 3) * 4;
            uint32_t ah[2][4], al[2][4];
            #pragma unroll
            for (int mf = 0; mf < 2; mf++) {
                int r0 = wm + mf * 16 + (lane >> 2);
                int r1 = r0 + 8;
                ah[mf][0] = lds32(fragaddr(base, r0, bo));
                ah[mf][1] = lds32(fragaddr(base, r1, bo));
                ah[mf][2] = lds32(fragaddr(base, r0, bo + 16));
                ah[mf][3] = lds32(fragaddr(base, r1, bo + 16));
                al[mf][0] = lds32(fragaddr(base + 16384u, r0, bo));
                al[mf][1] = lds32(fragaddr(base + 16384u, r1, bo));
                al[mf][2] = lds32(fragaddr(base + 16384u, r0, bo + 16));
                al[mf][3] = lds32(fragaddr(base + 16384u, r1, bo + 16));
            }
            #pragma unroll
            for (int nf = 0; nf < 8; nf++) {
                int nr = wn + nf * 8 + (lane >> 2);
                uint32_t bh0 = lds32(fragaddr(base + 32768u, nr, bo));
                uint32_t bh1 = lds32(fragaddr(base + 32768u, nr, bo + 16));
                uint32_t bl0 = lds32(fragaddr(base + 49152u, nr, bo));
                uint32_t bl1 = lds32(fragaddr(base + 49152u, nr, bo + 16));
                #pragma unroll
                for (int mf = 0; mf < 2; mf++) {
                    MMA_BF16(acc[mf][nf], ah[mf], bh0, bh1);
                    MMA_BF16(acc[mf][nf], al[mf], bh0, bh1);
                    MMA_BF16(acc[mf][nf], ah[mf], bl0, bl1);
                }
            }
        }
        __syncthreads();
    }

    // -------- epilogue --------
    if (Cfinal) {
        #pragma unroll
        for (int mf = 0; mf < 2; mf++) {
            int r0 = wm + mf * 16 + (lane >> 2);
            #pragma unroll
            for (int nf = 0; nf < 8; nf++) {
                int n = n0 + wn + nf * 8 + (lane & 3) * 2;
                float b0 = bias[n], b1 = bias[n + 1];
                float2 v0 = make_float2(acc[mf][nf][0] + b0, acc[mf][nf][1] + b1);
                float2 v1 = make_float2(acc[mf][nf][2] + b0, acc[mf][nf][3] + b1);
                *(float2*)&Cfinal[(size_t)r0 * Nf + n]       = v0;
                *(float2*)&Cfinal[(size_t)(r0 + 8) * Nf + n] = v1;
            }
        }
    } else {
        float* o = Cp + (size_t)(slice0 + blockIdx.y) * Np * 128;
        #pragma unroll
        for (int mf = 0; mf < 2; mf++) {
            int r0 = wm + mf * 16 + (lane >> 2);
            #pragma unroll
            for (int nf = 0; nf < 8; nf++) {
                int n = n0 + wn + nf * 8 + (lane & 3) * 2;
                *(float2*)&o[(size_t)r0 * Np + n] =
                    make_float2(acc[mf][nf][0], acc[mf][nf][1]);
                *(float2*)&o[(size_t)(r0 + 8) * Np + n] =
                    make_float2(acc[mf][nf][2], acc[mf][nf][3]);
            }
        }
    }
}

// ===================== small row-major kernels =============================

__global__ void embed_kernel(const int* __restrict__ step,
                             const float* __restrict__ emb,
                             float* __restrict__ x)
{
    int idx = blockIdx.x * blockDim.x + threadIdx.x;    // b*1024 + h
    if (idx >= Bq * Hq) return;
    int b = idx >> 10, h = idx & 1023;
    x[idx] = emb[(size_t)step[b] * Hq + h];
}

// split-K reduce + epilogue. EPI: 0 plain(+bias,+bias2), 1 mogrifier, 2 tanh
template<int EPI>
__global__ void epi_kernel(const float* __restrict__ Cp, int nsl, int N,
                           const float* __restrict__ bias,
                           const float* __restrict__ bias2,
                           float* __restrict__ out)
{
    int idx = blockIdx.x * blockDim.x + threadIdx.x;    // b*N + n
    if (idx >= N * 128) return;
    int n = idx & (N - 1);
    float v = 0.f;
    for (int s = 0; s < nsl; s++) v += Cp[(size_t)s * N * 128 + idx];
    if (bias)  v += bias[n];
    if (bias2) v += bias2[n];
    if (EPI == 0)      out[idx]  = v;
    else if (EPI == 1) out[idx] *= 2.f * sigf(v);
    else               out[idx]  = tanhf(v);
}

__global__ void lstm_pointwise(const float* __restrict__ gates,
                               const float* __restrict__ cprev,
                               float* __restrict__ h, int layer2)
{
    int idx = blockIdx.x * blockDim.x + threadIdx.x;    // b*1024 + hh
    if (idx >= Bq * Hq) return;
    int b = idx >> 10, hh = idx & 1023;
    size_t base = (size_t)b * 4096 + hh;
    float ig = gates[base];
    float fg = gates[base + 1024];
    float gg = gates[base + 2048];
    float og = gates[base + 3072];
    float c  = layer2 ? sigf(ig) * tanhf(gg)
                      : sigf(fg) * cprev[idx] + sigf(ig) * tanhf(gg);
    h[idx] = sigf(og) * tanhf(c);
}

__global__ void mog2_scale(const float* __restrict__ h,
                           const float* __restrict__ mog2_b,
                           float* __restrict__ x)
{
    int idx = blockIdx.x * blockDim.x + threadIdx.x;
    if (idx >= Bq * Hq) return;
    int j = idx & 1023;
    float f = 8.f * sigf(mog2_b[j]) * sigf(mog2_b[2 * Hq + j]) * sigf(mog2_b[4 * Hq + j]);
    x[idx] = h[idx] * f;
}

// ================= fused attention (online softmax, float4) ================
__global__ void __launch_bounds__(256)
attention_kernel(const float* __restrict__ rnn,   // [B][H]
                 const float* __restrict__ enc,   // [S][B][H]
                 float* __restrict__ ctx)         // [B][H]
{
    int b    = blockIdx.x;
    int tid  = threadIdx.x;
    int w    = tid >> 5;
    int lane = tid & 31;

    const float4* rb = (const float4*)(rnn + (size_t)b * Hq);
    float4 q[8];
    #pragma unroll
    for (int i = 0; i < 8; i++) q[i] = rb[i * 32 + lane];

    float m = -1e30f, l = 0.f;
    float4 acc[8];
    #pragma unroll
    for (int i = 0; i < 8; i++) acc[i] = make_float4(0.f, 0.f, 0.f, 0.f);

    for (int s = w; s < Sq; s += 8) {
        const float4* e = (const float4*)(enc + ((size_t)s * Bq + b) * Hq);
        float4 ev[8];
        float dot = 0.f;
        #pragma unroll
        for (int i = 0; i < 8; i++) {
            ev[i] = e[i * 32 + lane];
            dot += q[i].x * ev[i].x + q[i].y * ev[i].y
                 + q[i].z * ev[i].z + q[i].w * ev[i].w;
        }
        #pragma unroll
        for (int o = 16; o > 0; o >>= 1) dot += __shfl_xor_sync(0xffffffffu, dot, o);
        float mn   = fmaxf(m, dot);
        float corr = expf(m - mn);
        float p    = expf(dot - mn);
        l = l * corr + p;
        #pragma unroll
        for (int i = 0; i < 8; i++) {
            acc[i].x = acc[i].x * corr + p * ev[i].x;
            acc[i].y = acc[i].y * corr + p * ev[i].y;
            acc[i].z = acc[i].z * corr + p * ev[i].z;
            acc[i].w = acc[i].w * corr + p * ev[i].w;
        }
        m = mn;
    }

    __shared__ float sm[8], sl[8];
    __shared__ float sacc[8][Hq];
    #pragma unroll
    for (int i = 0; i < 8; i++) ((float4*)sacc[w])[i * 32 + lane] = acc[i];
    if (lane == 0) { sm[w] = m; sl[w] = l; }
    __syncthreads();

    float M = -1e30f;
    #pragma unroll
    for (int ww = 0; ww < 8; ww++) M = fmaxf(M, sm[ww]);
    float wexp[8], L = 0.f;
    #pragma unroll
    for (int ww = 0; ww < 8; ww++) { wexp[ww] = expf(sm[ww] - M); L += sl[ww] * wexp[ww]; }
    float invL = 1.f / L;

    for (int h = tid; h < Hq; h += 256) {
        float v = 0.f;
        #pragma unroll
        for (int ww = 0; ww < 8; ww++) v += sacc[ww][h] * wexp[ww];
        ctx[(size_t)b * Hq + h] = v * invL;
    }
}

// ------------------------------ row softmax --------------------------------
__global__ void softmax_kernel(const float* __restrict__ logits,
                               float* __restrict__ out)
{
    int b = blockIdx.x, tid = threadIdx.x;
    const float* row = logits + (size_t)b * Vq;
    __shared__ float red[256];

    float mx = -1e30f;
    for (int v = tid; v < Vq; v += 256) mx = fmaxf(mx, row[v]);
    red[tid] = mx; __syncthreads();
    for (int st = 128; st > 0; st >>= 1) {
        if (tid < st) red[tid] = fmaxf(red[tid], red[tid + st]);
        __syncthreads();
    }
    mx = red[0]; __syncthreads();

    float sum = 0.f;
    for (int v = tid; v < Vq; v += 256) sum += expf(row[v] - mx);
    red[tid] = sum; __syncthreads();
    for (int st = 128; st > 0; st >>= 1) {
        if (tid < st) red[tid] += red[tid + st];
        __syncthreads();
    }
    float inv = 1.f / red[0];

    float* o = out + (size_t)b * Vq;
    for (int v = tid; v < Vq; v += 256) o[v] = expf(row[v] - mx) * inv;
}

// ------------------------------- launch ------------------------------------
extern "C" void kernel_launch(void* const* d_in, const int* in_sizes, int n_in,
                              void* d_out, int out_size)
{
    const int*   step  = (const int*)  d_in[0];
    const float* enc   = (const float*)d_in[1];
    const float* h1    = (const float*)d_in[2];
    const float* c1    = (const float*)d_in[3];
    const float* emb   = (const float*)d_in[4];
    const float* mog1W = (const float*)d_in[5];
    const float* mog1b = (const float*)d_in[6];
    const float* Wih1  = (const float*)d_in[7];
    const float* Whh1  = (const float*)d_in[8];
    const float* bih1  = (const float*)d_in[9];
    const float* bhh1  = (const float*)d_in[10];
    const float* mog2b = (const float*)d_in[12];
    const float* Wih2  = (const float*)d_in[13];
    const float* bih2  = (const float*)d_in[15];
    const float* bhh2  = (const float*)d_in[16];
    const float* fcW   = (const float*)d_in[17];
    const float* fcb   = (const float*)d_in[18];
    const float* ccW   = (const float*)d_in[19];
    const float* ccb   = (const float*)d_in[20];
    const float* outW  = (const float*)d_in[21];
    const float* outb  = (const float*)d_in[22];
    float* out = (float*)d_out;

    float *x, *h, *rnn, *ctx, *cc, *gates, *part, *logits;
    cudaGetSymbolAddress((void**)&x,     g_x);
    cudaGetSymbolAddress((void**)&h,     g_h);
    cudaGetSymbolAddress((void**)&rnn,   g_rnn);
    cudaGetSymbolAddress((void**)&ctx,   g_ctx);
    cudaGetSymbolAddress((void**)&cc,    g_cc);
    cudaGetSymbolAddress((void**)&gates, g_gates);
    cudaGetSymbolAddress((void**)&part,  g_part);
    cudaGetSymbolAddress((void**)&logits,g_logits);

    cudaFuncSetAttribute(mma_gemm, cudaFuncAttributeMaxDynamicSharedMemorySize,
                         SMEM_BYTES);

    // state copy + embedding
    cudaMemcpyAsync(h, h1, (size_t)Bq * Hq * sizeof(float),
                    cudaMemcpyDeviceToDevice);
    embed_kernel<<<(Bq*Hq)/256, 256>>>(step, emb, x);

    // layer-1 mogrifier (N=1024, K=1024, KS=16 -> 128 blocks)
    for (int i = 0; i < 5; i++) {
        const float* src = (i % 2 == 0) ? h : x;
        float*       tgt = (i % 2 == 0) ? x : h;
        mma_gemm<<<dim3(8, 16), 256, SMEM_BYTES>>>(
            src, Hq, mog1W + (size_t)i * Hq * Hq, Hq, 0, 64,
            part, 0, Hq, nullptr, nullptr, 0);
        epi_kernel<1><<<(Hq*Bq)/256, 256>>>(part, 16, Hq, mog1b + i * Hq,
                                            nullptr, tgt);
    }

    // layer-1 LSTM gates (N=4096, K=1024 each, KS=4 -> 128 blocks each)
    mma_gemm<<<dim3(32, 4), 256, SMEM_BYTES>>>(x, Hq, Wih1, Hq, 0, 256,
                                               part, 0, 4*Hq, nullptr, nullptr, 0);
    mma_gemm<<<dim3(32, 4), 256, SMEM_BYTES>>>(h, Hq, Whh1, Hq, 0, 256,
                                               part, 4, 4*Hq, nullptr, nullptr, 0);
    epi_kernel<0><<<(4*Hq*Bq)/256, 256>>>(part, 8, 4*Hq, bih1, bhh1, gates);
    lstm_pointwise<<<(Hq*Bq)/256, 256>>>(gates, c1, h, 0);     // h := h1n

    // layer-2 (mogrifier collapses to bias-only scaling; h2 = c2 = 0)
    mog2_scale<<<(Hq*Bq)/256, 256>>>(h, mog2b, x);
    mma_gemm<<<dim3(32, 4), 256, SMEM_BYTES>>>(x, Hq, Wih2, Hq, 0, 256,
                                               part, 0, 4*Hq, nullptr, nullptr, 0);
    epi_kernel<0><<<(4*Hq*Bq)/256, 256>>>(part, 4, 4*Hq, bih2, bhh2, gates);
    lstm_pointwise<<<(Hq*Bq)/256, 256>>>(gates, nullptr, h, 1); // h := h2n

    // fc (N=1024, K=1024, KS=16)
    mma_gemm<<<dim3(8, 16), 256, SMEM_BYTES>>>(h, Hq, fcW, Hq, 0, 64,
                                               part, 0, Hq, nullptr, nullptr, 0);
    epi_kernel<0><<<(Hq*Bq)/256, 256>>>(part, 16, Hq, fcb, nullptr, rnn);

    // fused Luong attention (single pass over enc)
    attention_kernel<<<Bq, 256>>>(rnn, enc, ctx);

    // concat: [rnn, ctx] @ concat_W^T -> tanh  (2x K=1024, KS=8 each)
    mma_gemm<<<dim3(8, 8), 256, SMEM_BYTES>>>(rnn, Hq, ccW, 2*Hq, 0,   128,
                                              part, 0, Hq, nullptr, nullptr, 0);
    mma_gemm<<<dim3(8, 8), 256, SMEM_BYTES>>>(ctx, Hq, ccW, 2*Hq, Hq,  128,
                                              part, 8, Hq, nullptr, nullptr, 0);
    epi_kernel<2><<<(Hq*Bq)/256, 256>>>(part, 16, Hq, ccb, nullptr, cc);

    // output projection (N=32000, K=1024, fused bias) + softmax
    mma_gemm<<<dim3(Vq/128, 1), 256, SMEM_BYTES>>>(cc, Hq, outW, Hq, 0, 1024,
                                                   nullptr, 0, 0, outb, logits, Vq);
    softmax_kernel<<<Bq, 256>>>(logits, out);

    // hidden = h2n, row-major [B][H] appended after the softmax output
    if (out_size >= Bq*Vq + Bq*Hq)
        cudaMemcpyAsync(out + (size_t)Bq * Vq, h,
                        (size_t)Bq * Hq * sizeof(float),
                        cudaMemcpyDeviceToDevice);
}